// round 7
// baseline (speedup 1.0000x reference)
#include <cuda_runtime.h>
#include <cstdint>
#include <math.h>

#define Bn    2
#define Nn    384
#define HIDn  128
#define NHn   8
#define HDn   16
#define HROWS (Bn*Nn)          // 768
#define EROWS (Bn*Nn*Nn)       // 294912

// ---------------- scratch (static device globals; no allocations) ----------------
__device__ float g_h0[HROWS*HIDn];
__device__ float g_Q[HROWS*HIDn];
__device__ float g_K[HROWS*HIDn];
__device__ float g_V[HROWS*HIDn];
__device__ float g_eatt[(size_t)EROWS*NHn];   // (b,i,j,h) contiguous h
__device__ float g_amean[EROWS];
__device__ float g_attO[HROWS*HIDn];
__device__ float g_hW[HROWS*HIDn];

// ================= helpers =================
__device__ __forceinline__ float sigm(float x) { return 1.f / (1.f + __expf(-x)); }
__device__ __forceinline__ uint32_t pack_half2(float lo, float hi) {
  uint32_t r;
  asm("cvt.rn.f16x2.f32 %0, %1, %2;" : "=r"(r) : "f"(hi), "f"(lo));
  return r;
}
__device__ __forceinline__ void mma16(float* d, const uint4 a, const uint2 b) {
  asm volatile("mma.sync.aligned.m16n8k16.row.col.f32.f16.f16.f32 "
    "{%0,%1,%2,%3},{%4,%5,%6,%7},{%8,%9},{%0,%1,%2,%3};"
    : "+f"(d[0]), "+f"(d[1]), "+f"(d[2]), "+f"(d[3])
    : "r"(a.x), "r"(a.y), "r"(a.z), "r"(a.w), "r"(b.x), "r"(b.y));
}
__device__ __forceinline__ uint32_t smem_u32(const void* p) {
  uint32_t a;
  asm("{ .reg .u64 t; cvta.to.shared.u64 t, %1; cvt.u32.u64 %0, t; }" : "=r"(a) : "l"(p));
  return a;
}
__device__ __forceinline__ void cpa16(uint32_t dst, const void* src) {
  asm volatile("cp.async.cg.shared.global [%0], [%1], 16;" :: "r"(dst), "l"(src));
}
#define CPA_COMMIT() asm volatile("cp.async.commit_group;" ::: "memory")
#define CPA_WAIT0()  asm volatile("cp.async.wait_group 0;" ::: "memory")

// ---------------- kernel 1: h0 = node @ W_node + b_node ----------------
__global__ void k_lin_h0(const float* __restrict__ X, const float* __restrict__ W,
                         const float* __restrict__ bias) {
  int d = threadIdx.x;
  int r0 = blockIdx.x * 8;
  __shared__ float sX[8*128];
  for (int idx = d; idx < 8*128; idx += 128) sX[idx] = X[r0*128 + idx];
  __syncthreads();
  float acc[8];
  float bv = bias[d];
#pragma unroll
  for (int r = 0; r < 8; r++) acc[r] = bv;
  for (int k = 0; k < 128; k++) {
    float w = W[k*128 + d];
#pragma unroll
    for (int r = 0; r < 8; r++) acc[r] += sX[r*128 + k] * w;
  }
#pragma unroll
  for (int r = 0; r < 8; r++) g_h0[(r0 + r)*128 + d] = acc[r];
}

// ---------------- kernel 2: Q,K,V ----------------
__global__ void k_qkv(const float* __restrict__ Wq, const float* __restrict__ bq,
                      const float* __restrict__ Wk, const float* __restrict__ bk,
                      const float* __restrict__ Wv, const float* __restrict__ bv) {
  int d = threadIdx.x;
  int r0 = blockIdx.x * 8;
  __shared__ float sX[8*128];
  for (int idx = d; idx < 8*128; idx += 128) sX[idx] = g_h0[r0*128 + idx];
  __syncthreads();
  float aq[8], ak[8], av[8];
  float bqv = bq[d], bkv = bk[d], bvv = bv[d];
#pragma unroll
  for (int r = 0; r < 8; r++) { aq[r] = bqv; ak[r] = bkv; av[r] = bvv; }
  for (int k = 0; k < 128; k++) {
    float wq = Wq[k*128 + d], wk = Wk[k*128 + d], wv = Wv[k*128 + d];
#pragma unroll
    for (int r = 0; r < 8; r++) {
      float x = sX[r*128 + k];
      aq[r] += x*wq; ak[r] += x*wk; av[r] += x*wv;
    }
  }
#pragma unroll
  for (int r = 0; r < 8; r++) {
    g_Q[(r0 + r)*128 + d] = aq[r];
    g_K[(r0 + r)*128 + d] = ak[r];
    g_V[(r0 + r)*128 + d] = av[r];
  }
}

// ---------------- kernel 3: edge_attn via fp16 m16n8k16 mma.sync ----------------
// 512 threads / 16 warps. warp = (head h, m-group grp): B frags for head h in
// registers; grp selects m-tiles 4*grp..4*grp+3, processed as 2 sub-groups of 2
// (32 live accumulator regs). 4 warps/SMSP for phase overlap.
#define EA_GRID 144
#define EA_TPC  16
#define EA_THREADS 512
#define RAW_STRIDE  132
// smem: sA 32KB | raw 67584B | bias 1KB
#define EA_OFF_RAW  32768
#define EA_OFF_BIAS (32768 + 67584)
#define EA_SMEM     (EA_OFF_BIAS + 1024)

__global__ void __launch_bounds__(EA_THREADS, 1) k_edge_attn_mma(
    const float* __restrict__ E,
    const float* __restrict__ We, const float* __restrict__ Wg,
    const float* __restrict__ be, const float* __restrict__ bg) {
  extern __shared__ char smem[];
  uint4* sA4   = (uint4*)smem;                    // [(ks*8+mt)*32+lane]
  float* raw   = (float*)(smem + EA_OFF_RAW);     // [128][RAW_STRIDE]
  float* sBias = (float*)(smem + EA_OFF_BIAS);    // be | bg
  uint32_t rawu = smem_u32(raw);

  int tid = threadIdx.x;
  int wid = tid >> 5, lane = tid & 31;
  int h = wid & 7;                                // head
  int grp = wid >> 3;                             // m-group (0: mt 0-3, 1: mt 4-7)
  int g = lane >> 2, t4 = lane & 3;

  if (tid < 128) { sBias[tid] = be[tid]; sBias[128 + tid] = bg[tid]; }

  // ---- load B fragments into registers (staged via raw for coalescing) ----
  uint2 Bf[2][2][8];     // [EG][nti][ks]
#pragma unroll
  for (int half = 0; half < 2; half++) {
    const float* W = half ? Wg : We;
    __syncthreads();
    for (int idx = tid; idx < 128*32; idx += EA_THREADS) {
      int k = idx >> 5, c4 = idx & 31;
      float4 v = ((const float4*)W)[idx];
      *(float4*)(raw + k*RAW_STRIDE + c4*4) = v;
    }
    __syncthreads();
#pragma unroll
    for (int nti = 0; nti < 2; nti++) {
      int n = (2*h + nti)*8 + g;
#pragma unroll
      for (int ks = 0; ks < 8; ks++) {
        int k0 = ks*16 + 2*t4;
        uint32_t b0 = pack_half2(raw[k0*RAW_STRIDE + n],     raw[(k0+1)*RAW_STRIDE + n]);
        uint32_t b1 = pack_half2(raw[(k0+8)*RAW_STRIDE + n], raw[(k0+9)*RAW_STRIDE + n]);
        Bf[half][nti][ks] = make_uint2(b0, b1);
      }
    }
  }
  __syncthreads();   // raw free for E tiles

  // ---- pipeline: prefetch tile 0 ----
  {
    const float* Eg = E + ((size_t)blockIdx.x * EA_TPC) * 128 * 128;
    for (int idx = tid; idx < 4096; idx += EA_THREADS) {
      int m = idx >> 5, c4 = idx & 31;
      cpa16(rawu + (uint32_t)(m*RAW_STRIDE + c4*4)*4u, Eg + m*128 + c4*4);
    }
    CPA_COMMIT();
  }

  for (int t = 0; t < EA_TPC; t++) {
    size_t rowBase = ((size_t)blockIdx.x * EA_TPC + t) * 128;
    CPA_WAIT0();
    __syncthreads();   // raw ready; previous compute done with sA

    // convert raw fp32 -> fragment-order fp16 sA
#pragma unroll
    for (int it = 0; it < 4; it++) {
      int idx = tid + it*EA_THREADS;          // 0..2047
      int lf = idx & 31, mt = (idx >> 5) & 7, ks = idx >> 8;
      int gg = lf >> 2, tt = lf & 3;
      int m0 = mt*16 + gg;
      int k0 = ks*16 + 2*tt;
      float2 x0 = *(float2*)(raw + m0*RAW_STRIDE + k0);
      float2 x1 = *(float2*)(raw + (m0+8)*RAW_STRIDE + k0);
      float2 x2 = *(float2*)(raw + m0*RAW_STRIDE + k0 + 8);
      float2 x3 = *(float2*)(raw + (m0+8)*RAW_STRIDE + k0 + 8);
      uint4 v;
      v.x = pack_half2(x0.x, x0.y);
      v.y = pack_half2(x1.x, x1.y);
      v.z = pack_half2(x2.x, x2.y);
      v.w = pack_half2(x3.x, x3.y);
      sA4[idx] = v;
    }
    __syncthreads();   // sA ready; raw free

    if (t + 1 < EA_TPC) {
      const float* Eg = E + (rowBase + 128) * 128;
      for (int idx = tid; idx < 4096; idx += EA_THREADS) {
        int m = idx >> 5, c4 = idx & 31;
        cpa16(rawu + (uint32_t)(m*RAW_STRIDE + c4*4)*4u, Eg + m*128 + c4*4);
      }
      CPA_COMMIT();
    }

    // ---- compute: warp owns m-tiles [4*grp, 4*grp+3], 2 sub-groups of 2 ----
#pragma unroll
    for (int sub = 0; sub < 2; sub++) {
      int mt0 = grp*4 + sub*2;
      float aE[2][2][4], aG[2][2][4];
#pragma unroll
      for (int m2 = 0; m2 < 2; m2++)
#pragma unroll
        for (int nti = 0; nti < 2; nti++)
#pragma unroll
          for (int r = 0; r < 4; r++) { aE[m2][nti][r] = 0.f; aG[m2][nti][r] = 0.f; }

#pragma unroll
      for (int ks = 0; ks < 8; ks++) {
        uint4 a0 = sA4[(ks*8 + mt0 + 0)*32 + lane];
        uint4 a1 = sA4[(ks*8 + mt0 + 1)*32 + lane];
#pragma unroll
        for (int nti = 0; nti < 2; nti++) {
          mma16(aE[0][nti], a0, Bf[0][nti][ks]);
          mma16(aE[1][nti], a1, Bf[0][nti][ks]);
          mma16(aG[0][nti], a0, Bf[1][nti][ks]);
          mma16(aG[1][nti], a1, Bf[1][nti][ks]);
        }
      }

      // epilogue: bias + sigmoid gate + per-head reduce over 16 dims
#pragma unroll
      for (int m2 = 0; m2 < 2; m2++) {
        int mt = mt0 + m2;
        float s0 = 0.f, s1 = 0.f;
#pragma unroll
        for (int nti = 0; nti < 2; nti++) {
          int nb = (2*h + nti)*8 + 2*t4;
          float be0 = sBias[nb], be1 = sBias[nb+1];
          float bg0 = sBias[128+nb], bg1 = sBias[128+nb+1];
          s0 += (aE[m2][nti][0] + be0) * sigm(aG[m2][nti][0] + bg0)
              + (aE[m2][nti][1] + be1) * sigm(aG[m2][nti][1] + bg1);
          s1 += (aE[m2][nti][2] + be0) * sigm(aG[m2][nti][2] + bg0)
              + (aE[m2][nti][3] + be1) * sigm(aG[m2][nti][3] + bg1);
        }
        s0 += __shfl_xor_sync(0xffffffffu, s0, 1);
        s0 += __shfl_xor_sync(0xffffffffu, s0, 2);
        s1 += __shfl_xor_sync(0xffffffffu, s1, 1);
        s1 += __shfl_xor_sync(0xffffffffu, s1, 2);
        if (t4 == 0) {
          size_t r0 = rowBase + (size_t)mt*16 + g;
          g_eatt[r0*8 + h]       = s0;
          g_eatt[(r0 + 8)*8 + h] = s1;
        }
      }
    }
  }
}

// ---------------- kernel 4: scores + softmax + attn_mean + attn_out (tiled) ----------------
#define IPB 2
#define KPAD 132
__global__ void __launch_bounds__(256) k_attn2(const int* __restrict__ adj) {
  extern __shared__ float sm2[];
  float* sQ    = sm2;                   // IPB*128
  float* sPart = sQ + IPB*128;          // IPB*128
  float* sKV   = sPart + IPB*128;       // 64*KPAD
  float* sAtt  = sKV + 64*KPAD;         // IPB*8*Nn
  int tid = threadIdx.x;
  int bi0 = blockIdx.x * IPB;
  int b = bi0 / Nn;

  for (int idx = tid; idx < IPB*128; idx += 256) sQ[idx] = g_Q[bi0*128 + idx];
  __syncthreads();

  int jl = tid & 63, hp = tid >> 6;
  int h0 = hp*2;
  for (int jt = 0; jt < Nn/64; jt++) {
    for (int idx = tid; idx < 64*32; idx += 256) {
      int r = idx >> 5, c4 = idx & 31;
      float4 v = ((const float4*)(g_K + (size_t)(b*Nn + jt*64)*128))[idx];
      *(float4*)(sKV + r*KPAD + c4*4) = v;
    }
    __syncthreads();
    int j = jt*64 + jl;
    const float* kr = sKV + jl*KPAD;
    float a0[IPB], a1[IPB];
#pragma unroll
    for (int q = 0; q < IPB; q++) { a0[q] = 0.f; a1[q] = 0.f; }
#pragma unroll
    for (int d = 0; d < 16; d++) {
      float k0 = kr[h0*16 + d], k1 = kr[h0*16 + 16 + d];
#pragma unroll
      for (int q = 0; q < IPB; q++) {
        a0[q] += sQ[q*128 + h0*16 + d]      * k0;
        a1[q] += sQ[q*128 + h0*16 + 16 + d] * k1;
      }
    }
#pragma unroll
    for (int q = 0; q < IPB; q++) {
      int bi = bi0 + q;
      const float* er = g_eatt + ((size_t)bi*Nn + j)*8 + h0;
      float sc0 = a0[q]*0.25f + er[0];
      float sc1 = a1[q]*0.25f + er[1];
      if (adj[(size_t)bi*Nn + j] == 0) { sc0 = -1e9f; sc1 = -1e9f; }
      sAtt[(q*8 + h0)*Nn + j]     = sc0;
      sAtt[(q*8 + h0 + 1)*Nn + j] = sc1;
    }
    __syncthreads();
  }

  {
    int w = tid >> 5, lane = tid & 31;
    if (w < NHn) {
      for (int q = 0; q < IPB; q++) {
        float* rowp = sAtt + (q*8 + w)*Nn;
        float vals[12];
        float m = -1e30f;
#pragma unroll
        for (int c = 0; c < 12; c++) { vals[c] = rowp[lane + c*32]; m = fmaxf(m, vals[c]); }
#pragma unroll
        for (int off = 16; off > 0; off >>= 1) m = fmaxf(m, __shfl_xor_sync(0xffffffffu, m, off));
        float s = 0.f;
#pragma unroll
        for (int c = 0; c < 12; c++) { vals[c] = __expf(vals[c] - m); s += vals[c]; }
#pragma unroll
        for (int off = 16; off > 0; off >>= 1) s += __shfl_xor_sync(0xffffffffu, s, off);
        float inv = 1.f / s;
#pragma unroll
        for (int c = 0; c < 12; c++) rowp[lane + c*32] = vals[c] * inv;
      }
    }
  }
  __syncthreads();

  for (int idx = tid; idx < IPB*Nn; idx += 256) {
    int q = idx / Nn, j = idx % Nn;
    float s = 0.f;
#pragma unroll
    for (int h = 0; h < 8; h++) s += sAtt[(q*8 + h)*Nn + j];
    g_amean[(size_t)(bi0 + q)*Nn + j] = s * (1.f/NHn);
  }

  int d = tid & 127, half = tid >> 7;
  int hc = d >> 4;
  float acc[IPB];
#pragma unroll
  for (int q = 0; q < IPB; q++) acc[q] = 0.f;
  for (int jt = 0; jt < Nn/64; jt++) {
    __syncthreads();
    for (int idx = tid; idx < 64*32; idx += 256) {
      int r = idx >> 5, c4 = idx & 31;
      float4 v = ((const float4*)(g_V + (size_t)(b*Nn + jt*64)*128))[idx];
      *(float4*)(sKV + r*KPAD + c4*4) = v;
    }
    __syncthreads();
#pragma unroll 8
    for (int jj = half*32; jj < half*32 + 32; jj++) {
      float v = sKV[jj*KPAD + d];
      int j = jt*64 + jj;
#pragma unroll
      for (int q = 0; q < IPB; q++) acc[q] += sAtt[(q*8 + hc)*Nn + j] * v;
    }
  }
  __syncthreads();
  if (half == 1) {
#pragma unroll
    for (int q = 0; q < IPB; q++) sPart[q*128 + d] = acc[q];
  }
  __syncthreads();
  if (half == 0) {
#pragma unroll
    for (int q = 0; q < IPB; q++)
      g_attO[(size_t)(bi0 + q)*128 + d] = acc[q] + sPart[q*128 + d];
  }
}

// ---------------- kernel 5: h = LN(h0 + attO@W_out + b_out); hW = h @ W_eout ----------------
__global__ void k_hout(const float* __restrict__ Wout, const float* __restrict__ bout,
                       const float* __restrict__ g1, const float* __restrict__ be1,
                       const float* __restrict__ Weout, float* __restrict__ outH) {
  int row = blockIdx.x;
  int d = threadIdx.x;
  int lane = d & 31, w = d >> 5;
  __shared__ float sIn[128];
  __shared__ float sRow[128];
  __shared__ float sS[4], sQ2[4];
  sIn[d] = g_attO[row*128 + d];
  __syncthreads();
  float acc = bout[d];
#pragma unroll 4
  for (int k = 0; k < 128; k++) acc += sIn[k] * Wout[k*128 + d];
  float r = acc + g_h0[row*128 + d];
  float v = r, q = r*r;
#pragma unroll
  for (int off = 16; off > 0; off >>= 1) {
    v += __shfl_xor_sync(0xffffffffu, v, off);
    q += __shfl_xor_sync(0xffffffffu, q, off);
  }
  if (lane == 0) { sS[w] = v; sQ2[w] = q; }
  __syncthreads();
  float tot  = sS[0] + sS[1] + sS[2] + sS[3];
  float totq = sQ2[0] + sQ2[1] + sQ2[2] + sQ2[3];
  float mean = tot * (1.f/128.f);
  float var  = totq * (1.f/128.f) - mean*mean;
  float y = (r - mean) * rsqrtf(var + 1e-5f) * g1[d] + be1[d];
  outH[row*128 + d] = y;
  sRow[d] = y;
  __syncthreads();
  float acc2 = 0.f;
#pragma unroll 4
  for (int k = 0; k < 128; k++) acc2 += sRow[k] * Weout[k*128 + d];
  g_hW[row*128 + d] = acc2;
}

// ---------------- kernel 6: edge_out = LN(E + amean*0.5*(hW_i+hW_j) + b_eout) ----------------
__global__ void k_edge_out(const float* __restrict__ Ef, const float* __restrict__ beout,
                           const float* __restrict__ g2, const float* __restrict__ be2,
                           float* __restrict__ outE) {
  int warp = threadIdx.x >> 5, lane = threadIdx.x & 31;
  size_t row = (size_t)blockIdx.x * 8 + warp;
  int b  = (int)(row / (Nn*Nn));
  int ij = (int)(row % (Nn*Nn));
  int i = ij / Nn, j = ij % Nn;
  float am = g_amean[row] * 0.5f;
  float4 e  = ((const float4*)(Ef + row*128))[lane];
  float4 ui = ((const float4*)(g_hW + (size_t)(b*Nn + i)*128))[lane];
  float4 uj = ((const float4*)(g_hW + (size_t)(b*Nn + j)*128))[lane];
  float4 bo = ((const float4*)beout)[lane];
  float v0 = e.x + am*(ui.x + uj.x) + bo.x;
  float v1 = e.y + am*(ui.y + uj.y) + bo.y;
  float v2 = e.z + am*(ui.z + uj.z) + bo.z;
  float v3 = e.w + am*(ui.w + uj.w) + bo.w;
  float s = v0 + v1 + v2 + v3;
  float q = v0*v0 + v1*v1 + v2*v2 + v3*v3;
#pragma unroll
  for (int off = 16; off > 0; off >>= 1) {
    s += __shfl_xor_sync(0xffffffffu, s, off);
    q += __shfl_xor_sync(0xffffffffu, q, off);
  }
  float mean = s * (1.f/128.f);
  float var  = q * (1.f/128.f) - mean*mean;
  float inv  = rsqrtf(var + 1e-5f);
  float4 gg = ((const float4*)g2)[lane];
  float4 bb = ((const float4*)be2)[lane];
  float4 o;
  o.x = (v0 - mean)*inv*gg.x + bb.x;
  o.y = (v1 - mean)*inv*gg.y + bb.y;
  o.z = (v2 - mean)*inv*gg.z + bb.z;
  o.w = (v3 - mean)*inv*gg.w + bb.w;
  ((float4*)outE)[row*32 + lane] = o;
}

// ---------------- launcher ----------------
extern "C" void kernel_launch(void* const* d_in, const int* in_sizes, int n_in,
                              void* d_out, int out_size) {
  const float* node   = (const float*)d_in[0];
  const float* edge   = (const float*)d_in[1];
  const int*   adj    = (const int*)  d_in[2];
  const float* W_node = (const float*)d_in[3];  const float* b_node = (const float*)d_in[4];
  const float* W_q    = (const float*)d_in[5];  const float* b_q    = (const float*)d_in[6];
  const float* W_k    = (const float*)d_in[7];  const float* b_k    = (const float*)d_in[8];
  const float* W_v    = (const float*)d_in[9];  const float* b_v    = (const float*)d_in[10];
  const float* W_edge = (const float*)d_in[11]; const float* b_edge = (const float*)d_in[12];
  const float* W_gate = (const float*)d_in[13]; const float* b_gate = (const float*)d_in[14];
  const float* W_out  = (const float*)d_in[15]; const float* b_out  = (const float*)d_in[16];
  const float* W_eout = (const float*)d_in[17]; const float* b_eout = (const float*)d_in[18];
  const float* g1     = (const float*)d_in[19]; const float* be1    = (const float*)d_in[20];
  const float* g2     = (const float*)d_in[21]; const float* be2    = (const float*)d_in[22];

  float* outH = (float*)d_out;
  float* outE = outH + HROWS*HIDn;

  cudaFuncSetAttribute(k_edge_attn_mma, cudaFuncAttributeMaxDynamicSharedMemorySize, EA_SMEM);
  cudaFuncSetAttribute(k_attn2, cudaFuncAttributeMaxDynamicSharedMemorySize, 128*1024);

  int attn_smem = (IPB*128 + IPB*128 + 64*KPAD + IPB*8*Nn) * 4;

  k_lin_h0<<<HROWS/8, 128>>>(node, W_node, b_node);
  k_qkv<<<HROWS/8, 128>>>(W_q, b_q, W_k, b_k, W_v, b_v);
  k_edge_attn_mma<<<EA_GRID, EA_THREADS, EA_SMEM>>>(edge, W_edge, W_gate, b_edge, b_gate);
  k_attn2<<<HROWS/IPB, 256, attn_smem>>>(adj);
  k_hout<<<HROWS, 128>>>(W_out, b_out, g1, be1, W_eout, outH);
  k_edge_out<<<EROWS/8, 256>>>(edge, b_eout, g2, be2, outE);
}

// round 8
// speedup vs baseline: 1.3825x; 1.3825x over previous
#include <cuda_runtime.h>
#include <cstdint>
#include <math.h>

#define Bn    2
#define Nn    384
#define HIDn  128
#define NHn   8
#define HDn   16
#define HROWS (Bn*Nn)          // 768
#define EROWS (Bn*Nn*Nn)       // 294912

// ---------------- scratch (static device globals; no allocations) ----------------
__device__ float g_h0[HROWS*HIDn];
__device__ float g_Q[HROWS*HIDn];
__device__ float g_K[HROWS*HIDn];
__device__ float g_V[HROWS*HIDn];
__device__ float g_eatt[(size_t)EROWS*NHn];   // (b,i,j,h) contiguous h
__device__ float g_amean[EROWS];
__device__ float g_attO[HROWS*HIDn];
__device__ float g_hW[HROWS*HIDn];

// ================= helpers =================
__device__ __forceinline__ float sigm(float x) { return 1.f / (1.f + __expf(-x)); }
__device__ __forceinline__ uint32_t pack_half2(float lo, float hi) {
  uint32_t r;
  asm("cvt.rn.f16x2.f32 %0, %1, %2;" : "=r"(r) : "f"(hi), "f"(lo));
  return r;
}
__device__ __forceinline__ void mma16(float* d, const uint4 a, const uint2 b) {
  asm volatile("mma.sync.aligned.m16n8k16.row.col.f32.f16.f16.f32 "
    "{%0,%1,%2,%3},{%4,%5,%6,%7},{%8,%9},{%0,%1,%2,%3};"
    : "+f"(d[0]), "+f"(d[1]), "+f"(d[2]), "+f"(d[3])
    : "r"(a.x), "r"(a.y), "r"(a.z), "r"(a.w), "r"(b.x), "r"(b.y));
}
__device__ __forceinline__ uint32_t smem_u32(const void* p) {
  uint32_t a;
  asm("{ .reg .u64 t; cvta.to.shared.u64 t, %1; cvt.u32.u64 %0, t; }" : "=r"(a) : "l"(p));
  return a;
}
__device__ __forceinline__ void cpa16(uint32_t dst, const void* src) {
  asm volatile("cp.async.cg.shared.global [%0], [%1], 16;" :: "r"(dst), "l"(src));
}
#define CPA_COMMIT() asm volatile("cp.async.commit_group;" ::: "memory")
#define CPA_WAIT0()  asm volatile("cp.async.wait_group 0;" ::: "memory")

// ---------------- kernel 1: h0 = node @ W_node + b_node ----------------
__global__ void k_lin_h0(const float* __restrict__ X, const float* __restrict__ W,
                         const float* __restrict__ bias) {
  int d = threadIdx.x;
  int r0 = blockIdx.x * 8;
  __shared__ float sX[8*128];
  for (int idx = d; idx < 8*128; idx += 128) sX[idx] = X[r0*128 + idx];
  __syncthreads();
  float acc[8];
  float bv = bias[d];
#pragma unroll
  for (int r = 0; r < 8; r++) acc[r] = bv;
  for (int k = 0; k < 128; k++) {
    float w = W[k*128 + d];
#pragma unroll
    for (int r = 0; r < 8; r++) acc[r] += sX[r*128 + k] * w;
  }
#pragma unroll
  for (int r = 0; r < 8; r++) g_h0[(r0 + r)*128 + d] = acc[r];
}

// ---------------- kernel 2: Q,K,V ----------------
__global__ void k_qkv(const float* __restrict__ Wq, const float* __restrict__ bq,
                      const float* __restrict__ Wk, const float* __restrict__ bk,
                      const float* __restrict__ Wv, const float* __restrict__ bv) {
  int d = threadIdx.x;
  int r0 = blockIdx.x * 8;
  __shared__ float sX[8*128];
  for (int idx = d; idx < 8*128; idx += 128) sX[idx] = g_h0[r0*128 + idx];
  __syncthreads();
  float aq[8], ak[8], av[8];
  float bqv = bq[d], bkv = bk[d], bvv = bv[d];
#pragma unroll
  for (int r = 0; r < 8; r++) { aq[r] = bqv; ak[r] = bkv; av[r] = bvv; }
  for (int k = 0; k < 128; k++) {
    float wq = Wq[k*128 + d], wk = Wk[k*128 + d], wv = Wv[k*128 + d];
#pragma unroll
    for (int r = 0; r < 8; r++) {
      float x = sX[r*128 + k];
      aq[r] += x*wq; ak[r] += x*wk; av[r] += x*wv;
    }
  }
#pragma unroll
  for (int r = 0; r < 8; r++) {
    g_Q[(r0 + r)*128 + d] = aq[r];
    g_K[(r0 + r)*128 + d] = ak[r];
    g_V[(r0 + r)*128 + d] = av[r];
  }
}

// ---------------- kernel 3: edge_attn via fp16 m16n8k16 mma.sync ----------------
// 256 threads, warp = head, B fragments register-resident (round-6 structure).
// 288 CTAs x 8 tiles -> 2 CTAs/SM: cross-CTA overlap of the barrier-separated
// convert/LDS/MUFU phases with the other CTA's HMMA phase.
#define EA_GRID 288
#define EA_TPC  8
#define RAW_STRIDE  132
// smem: sA 32KB | raw 67584B | bias 1KB  (= 101376B; two CTAs fit in 228KB)
#define EA_OFF_RAW  32768
#define EA_OFF_BIAS (32768 + 67584)
#define EA_SMEM     (EA_OFF_BIAS + 1024)

__global__ void __launch_bounds__(256) k_edge_attn_mma(
    const float* __restrict__ E,
    const float* __restrict__ We, const float* __restrict__ Wg,
    const float* __restrict__ be, const float* __restrict__ bg) {
  extern __shared__ char smem[];
  uint4* sA4   = (uint4*)smem;                    // [(ks*8+mt)*32+lane]
  float* raw   = (float*)(smem + EA_OFF_RAW);     // [128][RAW_STRIDE]
  float* sBias = (float*)(smem + EA_OFF_BIAS);    // be | bg
  uint32_t rawu = smem_u32(raw);

  int tid = threadIdx.x;
  int h = tid >> 5, lane = tid & 31;              // warp == head
  int g = lane >> 2, t4 = lane & 3;

  if (tid < 128) { sBias[tid] = be[tid]; sBias[128 + tid] = bg[tid]; }

  // ---- load B fragments into registers (staged via raw for coalescing) ----
  uint2 Bf[2][2][8];     // [EG][nti][ks]
#pragma unroll
  for (int half = 0; half < 2; half++) {
    const float* W = half ? Wg : We;
    __syncthreads();
    for (int idx = tid; idx < 128*32; idx += 256) {
      int k = idx >> 5, c4 = idx & 31;
      float4 v = ((const float4*)W)[idx];
      *(float4*)(raw + k*RAW_STRIDE + c4*4) = v;
    }
    __syncthreads();
#pragma unroll
    for (int nti = 0; nti < 2; nti++) {
      int n = (2*h + nti)*8 + g;
#pragma unroll
      for (int ks = 0; ks < 8; ks++) {
        int k0 = ks*16 + 2*t4;
        uint32_t b0 = pack_half2(raw[k0*RAW_STRIDE + n],     raw[(k0+1)*RAW_STRIDE + n]);
        uint32_t b1 = pack_half2(raw[(k0+8)*RAW_STRIDE + n], raw[(k0+9)*RAW_STRIDE + n]);
        Bf[half][nti][ks] = make_uint2(b0, b1);
      }
    }
  }
  __syncthreads();   // raw free for E tiles

  // ---- pipeline: prefetch tile 0 ----
  {
    const float* Eg = E + ((size_t)blockIdx.x * EA_TPC) * 128 * 128;
    for (int idx = tid; idx < 4096; idx += 256) {
      int m = idx >> 5, c4 = idx & 31;
      cpa16(rawu + (uint32_t)(m*RAW_STRIDE + c4*4)*4u, Eg + m*128 + c4*4);
    }
    CPA_COMMIT();
  }

  for (int t = 0; t < EA_TPC; t++) {
    size_t rowBase = ((size_t)blockIdx.x * EA_TPC + t) * 128;
    CPA_WAIT0();
    __syncthreads();   // raw ready; previous compute done with sA

    // convert raw fp32 -> fragment-order fp16 sA
#pragma unroll
    for (int it = 0; it < 8; it++) {
      int idx = tid + it*256;                 // 0..2047
      int lf = idx & 31, mt = (idx >> 5) & 7, ks = idx >> 8;
      int gg = lf >> 2, tt = lf & 3;
      int m0 = mt*16 + gg;
      int k0 = ks*16 + 2*tt;
      float2 x0 = *(float2*)(raw + m0*RAW_STRIDE + k0);
      float2 x1 = *(float2*)(raw + (m0+8)*RAW_STRIDE + k0);
      float2 x2 = *(float2*)(raw + m0*RAW_STRIDE + k0 + 8);
      float2 x3 = *(float2*)(raw + (m0+8)*RAW_STRIDE + k0 + 8);
      uint4 v;
      v.x = pack_half2(x0.x, x0.y);
      v.y = pack_half2(x1.x, x1.y);
      v.z = pack_half2(x2.x, x2.y);
      v.w = pack_half2(x3.x, x3.y);
      sA4[idx] = v;
    }
    __syncthreads();   // sA ready; raw free

    if (t + 1 < EA_TPC) {
      const float* Eg = E + (rowBase + 128) * 128;
      for (int idx = tid; idx < 4096; idx += 256) {
        int m = idx >> 5, c4 = idx & 31;
        cpa16(rawu + (uint32_t)(m*RAW_STRIDE + c4*4)*4u, Eg + m*128 + c4*4);
      }
      CPA_COMMIT();
    }

    // ---- compute: two groups of 4 m-tiles; all-register B ----
#pragma unroll
    for (int grp = 0; grp < 2; grp++) {
      float aE[4][2][4], aG[4][2][4];
#pragma unroll
      for (int m4 = 0; m4 < 4; m4++)
#pragma unroll
        for (int nti = 0; nti < 2; nti++)
#pragma unroll
          for (int r = 0; r < 4; r++) { aE[m4][nti][r] = 0.f; aG[m4][nti][r] = 0.f; }

#pragma unroll
      for (int ks = 0; ks < 8; ks++) {
        uint4 a[4];
#pragma unroll
        for (int m4 = 0; m4 < 4; m4++)
          a[m4] = sA4[(ks*8 + grp*4 + m4)*32 + lane];
#pragma unroll
        for (int m4 = 0; m4 < 4; m4++) {
#pragma unroll
          for (int nti = 0; nti < 2; nti++) {
            mma16(aE[m4][nti], a[m4], Bf[0][nti][ks]);
            mma16(aG[m4][nti], a[m4], Bf[1][nti][ks]);
          }
        }
      }

      // epilogue: bias + sigmoid gate + per-head reduce over 16 dims
#pragma unroll
      for (int m4 = 0; m4 < 4; m4++) {
        int mt = grp*4 + m4;
        float s0 = 0.f, s1 = 0.f;
#pragma unroll
        for (int nti = 0; nti < 2; nti++) {
          int nb = (2*h + nti)*8 + 2*t4;
          float be0 = sBias[nb], be1 = sBias[nb+1];
          float bg0 = sBias[128+nb], bg1 = sBias[128+nb+1];
          s0 += (aE[m4][nti][0] + be0) * sigm(aG[m4][nti][0] + bg0)
              + (aE[m4][nti][1] + be1) * sigm(aG[m4][nti][1] + bg1);
          s1 += (aE[m4][nti][2] + be0) * sigm(aG[m4][nti][2] + bg0)
              + (aE[m4][nti][3] + be1) * sigm(aG[m4][nti][3] + bg1);
        }
        s0 += __shfl_xor_sync(0xffffffffu, s0, 1);
        s0 += __shfl_xor_sync(0xffffffffu, s0, 2);
        s1 += __shfl_xor_sync(0xffffffffu, s1, 1);
        s1 += __shfl_xor_sync(0xffffffffu, s1, 2);
        if (t4 == 0) {
          size_t r0 = rowBase + (size_t)mt*16 + g;
          g_eatt[r0*8 + h]       = s0;
          g_eatt[(r0 + 8)*8 + h] = s1;
        }
      }
    }
  }
}

// ---------------- kernel 4: scores + softmax + attn_mean + attn_out (tiled) ----------------
#define IPB 2
#define KPAD 132
__global__ void __launch_bounds__(256) k_attn2(const int* __restrict__ adj) {
  extern __shared__ float sm2[];
  float* sQ    = sm2;                   // IPB*128
  float* sPart = sQ + IPB*128;          // IPB*128
  float* sKV   = sPart + IPB*128;       // 64*KPAD
  float* sAtt  = sKV + 64*KPAD;         // IPB*8*Nn
  int tid = threadIdx.x;
  int bi0 = blockIdx.x * IPB;
  int b = bi0 / Nn;

  for (int idx = tid; idx < IPB*128; idx += 256) sQ[idx] = g_Q[bi0*128 + idx];
  __syncthreads();

  int jl = tid & 63, hp = tid >> 6;
  int h0 = hp*2;
  for (int jt = 0; jt < Nn/64; jt++) {
    for (int idx = tid; idx < 64*32; idx += 256) {
      int r = idx >> 5, c4 = idx & 31;
      float4 v = ((const float4*)(g_K + (size_t)(b*Nn + jt*64)*128))[idx];
      *(float4*)(sKV + r*KPAD + c4*4) = v;
    }
    __syncthreads();
    int j = jt*64 + jl;
    const float* kr = sKV + jl*KPAD;
    float a0[IPB], a1[IPB];
#pragma unroll
    for (int q = 0; q < IPB; q++) { a0[q] = 0.f; a1[q] = 0.f; }
#pragma unroll
    for (int d = 0; d < 16; d++) {
      float k0 = kr[h0*16 + d], k1 = kr[h0*16 + 16 + d];
#pragma unroll
      for (int q = 0; q < IPB; q++) {
        a0[q] += sQ[q*128 + h0*16 + d]      * k0;
        a1[q] += sQ[q*128 + h0*16 + 16 + d] * k1;
      }
    }
#pragma unroll
    for (int q = 0; q < IPB; q++) {
      int bi = bi0 + q;
      const float* er = g_eatt + ((size_t)bi*Nn + j)*8 + h0;
      float sc0 = a0[q]*0.25f + er[0];
      float sc1 = a1[q]*0.25f + er[1];
      if (adj[(size_t)bi*Nn + j] == 0) { sc0 = -1e9f; sc1 = -1e9f; }
      sAtt[(q*8 + h0)*Nn + j]     = sc0;
      sAtt[(q*8 + h0 + 1)*Nn + j] = sc1;
    }
    __syncthreads();
  }

  {
    int w = tid >> 5, lane = tid & 31;
    if (w < NHn) {
      for (int q = 0; q < IPB; q++) {
        float* rowp = sAtt + (q*8 + w)*Nn;
        float vals[12];
        float m = -1e30f;
#pragma unroll
        for (int c = 0; c < 12; c++) { vals[c] = rowp[lane + c*32]; m = fmaxf(m, vals[c]); }
#pragma unroll
        for (int off = 16; off > 0; off >>= 1) m = fmaxf(m, __shfl_xor_sync(0xffffffffu, m, off));
        float s = 0.f;
#pragma unroll
        for (int c = 0; c < 12; c++) { vals[c] = __expf(vals[c] - m); s += vals[c]; }
#pragma unroll
        for (int off = 16; off > 0; off >>= 1) s += __shfl_xor_sync(0xffffffffu, s, off);
        float inv = 1.f / s;
#pragma unroll
        for (int c = 0; c < 12; c++) rowp[lane + c*32] = vals[c] * inv;
      }
    }
  }
  __syncthreads();

  for (int idx = tid; idx < IPB*Nn; idx += 256) {
    int q = idx / Nn, j = idx % Nn;
    float s = 0.f;
#pragma unroll
    for (int h = 0; h < 8; h++) s += sAtt[(q*8 + h)*Nn + j];
    g_amean[(size_t)(bi0 + q)*Nn + j] = s * (1.f/NHn);
  }

  int d = tid & 127, half = tid >> 7;
  int hc = d >> 4;
  float acc[IPB];
#pragma unroll
  for (int q = 0; q < IPB; q++) acc[q] = 0.f;
  for (int jt = 0; jt < Nn/64; jt++) {
    __syncthreads();
    for (int idx = tid; idx < 64*32; idx += 256) {
      int r = idx >> 5, c4 = idx & 31;
      float4 v = ((const float4*)(g_V + (size_t)(b*Nn + jt*64)*128))[idx];
      *(float4*)(sKV + r*KPAD + c4*4) = v;
    }
    __syncthreads();
#pragma unroll 8
    for (int jj = half*32; jj < half*32 + 32; jj++) {
      float v = sKV[jj*KPAD + d];
      int j = jt*64 + jj;
#pragma unroll
      for (int q = 0; q < IPB; q++) acc[q] += sAtt[(q*8 + hc)*Nn + j] * v;
    }
  }
  __syncthreads();
  if (half == 1) {
#pragma unroll
    for (int q = 0; q < IPB; q++) sPart[q*128 + d] = acc[q];
  }
  __syncthreads();
  if (half == 0) {
#pragma unroll
    for (int q = 0; q < IPB; q++)
      g_attO[(size_t)(bi0 + q)*128 + d] = acc[q] + sPart[q*128 + d];
  }
}

// ---------------- kernel 5: h = LN(h0 + attO@W_out + b_out); hW = h @ W_eout ----------------
__global__ void k_hout(const float* __restrict__ Wout, const float* __restrict__ bout,
                       const float* __restrict__ g1, const float* __restrict__ be1,
                       const float* __restrict__ Weout, float* __restrict__ outH) {
  int row = blockIdx.x;
  int d = threadIdx.x;
  int lane = d & 31, w = d >> 5;
  __shared__ float sIn[128];
  __shared__ float sRow[128];
  __shared__ float sS[4], sQ2[4];
  sIn[d] = g_attO[row*128 + d];
  __syncthreads();
  float acc = bout[d];
#pragma unroll 4
  for (int k = 0; k < 128; k++) acc += sIn[k] * Wout[k*128 + d];
  float r = acc + g_h0[row*128 + d];
  float v = r, q = r*r;
#pragma unroll
  for (int off = 16; off > 0; off >>= 1) {
    v += __shfl_xor_sync(0xffffffffu, v, off);
    q += __shfl_xor_sync(0xffffffffu, q, off);
  }
  if (lane == 0) { sS[w] = v; sQ2[w] = q; }
  __syncthreads();
  float tot  = sS[0] + sS[1] + sS[2] + sS[3];
  float totq = sQ2[0] + sQ2[1] + sQ2[2] + sQ2[3];
  float mean = tot * (1.f/128.f);
  float var  = totq * (1.f/128.f) - mean*mean;
  float y = (r - mean) * rsqrtf(var + 1e-5f) * g1[d] + be1[d];
  outH[row*128 + d] = y;
  sRow[d] = y;
  __syncthreads();
  float acc2 = 0.f;
#pragma unroll 4
  for (int k = 0; k < 128; k++) acc2 += sRow[k] * Weout[k*128 + d];
  g_hW[row*128 + d] = acc2;
}

// ---------------- kernel 6: edge_out = LN(E + amean*0.5*(hW_i+hW_j) + b_eout) ----------------
__global__ void k_edge_out(const float* __restrict__ Ef, const float* __restrict__ beout,
                           const float* __restrict__ g2, const float* __restrict__ be2,
                           float* __restrict__ outE) {
  int warp = threadIdx.x >> 5, lane = threadIdx.x & 31;
  size_t row = (size_t)blockIdx.x * 8 + warp;
  int b  = (int)(row / (Nn*Nn));
  int ij = (int)(row % (Nn*Nn));
  int i = ij / Nn, j = ij % Nn;
  float am = g_amean[row] * 0.5f;
  float4 e  = ((const float4*)(Ef + row*128))[lane];
  float4 ui = ((const float4*)(g_hW + (size_t)(b*Nn + i)*128))[lane];
  float4 uj = ((const float4*)(g_hW + (size_t)(b*Nn + j)*128))[lane];
  float4 bo = ((const float4*)beout)[lane];
  float v0 = e.x + am*(ui.x + uj.x) + bo.x;
  float v1 = e.y + am*(ui.y + uj.y) + bo.y;
  float v2 = e.z + am*(ui.z + uj.z) + bo.z;
  float v3 = e.w + am*(ui.w + uj.w) + bo.w;
  float s = v0 + v1 + v2 + v3;
  float q = v0*v0 + v1*v1 + v2*v2 + v3*v3;
#pragma unroll
  for (int off = 16; off > 0; off >>= 1) {
    s += __shfl_xor_sync(0xffffffffu, s, off);
    q += __shfl_xor_sync(0xffffffffu, q, off);
  }
  float mean = s * (1.f/128.f);
  float var  = q * (1.f/128.f) - mean*mean;
  float inv  = rsqrtf(var + 1e-5f);
  float4 gg = ((const float4*)g2)[lane];
  float4 bb = ((const float4*)be2)[lane];
  float4 o;
  o.x = (v0 - mean)*inv*gg.x + bb.x;
  o.y = (v1 - mean)*inv*gg.y + bb.y;
  o.z = (v2 - mean)*inv*gg.z + bb.z;
  o.w = (v3 - mean)*inv*gg.w + bb.w;
  ((float4*)outE)[row*32 + lane] = o;
}

// ---------------- launcher ----------------
extern "C" void kernel_launch(void* const* d_in, const int* in_sizes, int n_in,
                              void* d_out, int out_size) {
  const float* node   = (const float*)d_in[0];
  const float* edge   = (const float*)d_in[1];
  const int*   adj    = (const int*)  d_in[2];
  const float* W_node = (const float*)d_in[3];  const float* b_node = (const float*)d_in[4];
  const float* W_q    = (const float*)d_in[5];  const float* b_q    = (const float*)d_in[6];
  const float* W_k    = (const float*)d_in[7];  const float* b_k    = (const float*)d_in[8];
  const float* W_v    = (const float*)d_in[9];  const float* b_v    = (const float*)d_in[10];
  const float* W_edge = (const float*)d_in[11]; const float* b_edge = (const float*)d_in[12];
  const float* W_gate = (const float*)d_in[13]; const float* b_gate = (const float*)d_in[14];
  const float* W_out  = (const float*)d_in[15]; const float* b_out  = (const float*)d_in[16];
  const float* W_eout = (const float*)d_in[17]; const float* b_eout = (const float*)d_in[18];
  const float* g1     = (const float*)d_in[19]; const float* be1    = (const float*)d_in[20];
  const float* g2     = (const float*)d_in[21]; const float* be2    = (const float*)d_in[22];

  float* outH = (float*)d_out;
  float* outE = outH + HROWS*HIDn;

  cudaFuncSetAttribute(k_edge_attn_mma, cudaFuncAttributeMaxDynamicSharedMemorySize, EA_SMEM);
  cudaFuncSetAttribute(k_attn2, cudaFuncAttributeMaxDynamicSharedMemorySize, 128*1024);

  int attn_smem = (IPB*128 + IPB*128 + 64*KPAD + IPB*8*Nn) * 4;

  k_lin_h0<<<HROWS/8, 128>>>(node, W_node, b_node);
  k_qkv<<<HROWS/8, 128>>>(W_q, b_q, W_k, b_k, W_v, b_v);
  k_edge_attn_mma<<<EA_GRID, 256, EA_SMEM>>>(edge, W_edge, W_gate, b_edge, b_gate);
  k_attn2<<<HROWS/IPB, 256, attn_smem>>>(adj);
  k_hout<<<HROWS, 128>>>(W_out, b_out, g1, be1, W_eout, outH);
  k_edge_out<<<EROWS/8, 256>>>(edge, b_eout, g2, be2, outE);
}

// round 9
// speedup vs baseline: 1.6418x; 1.1875x over previous
#include <cuda_runtime.h>
#include <cstdint>
#include <math.h>

#define Bn    2
#define Nn    384
#define HIDn  128
#define NHn   8
#define HDn   16
#define HROWS (Bn*Nn)          // 768
#define EROWS (Bn*Nn*Nn)       // 294912

// ---------------- scratch (static device globals; no allocations) ----------------
__device__ float g_h0[HROWS*HIDn];
__device__ float g_Q[HROWS*HIDn];
__device__ float g_K[HROWS*HIDn];
__device__ float g_V[HROWS*HIDn];
__device__ float g_eatt[(size_t)EROWS*NHn];   // (b,i,j,h) contiguous h
__device__ float g_amean[EROWS];
__device__ float g_attO[HROWS*HIDn];
__device__ float g_hW[HROWS*HIDn];
__device__ int   g_cnt;
__device__ int   g_ntiles;
__device__ int   g_rowidx[EROWS + 128];

// ================= helpers =================
__device__ __forceinline__ float sigm(float x) { return 1.f / (1.f + __expf(-x)); }
__device__ __forceinline__ uint32_t pack_half2(float lo, float hi) {
  uint32_t r;
  asm("cvt.rn.f16x2.f32 %0, %1, %2;" : "=r"(r) : "f"(hi), "f"(lo));
  return r;
}
__device__ __forceinline__ void mma16(float* d, const uint4 a, const uint2 b) {
  asm volatile("mma.sync.aligned.m16n8k16.row.col.f32.f16.f16.f32 "
    "{%0,%1,%2,%3},{%4,%5,%6,%7},{%8,%9},{%0,%1,%2,%3};"
    : "+f"(d[0]), "+f"(d[1]), "+f"(d[2]), "+f"(d[3])
    : "r"(a.x), "r"(a.y), "r"(a.z), "r"(a.w), "r"(b.x), "r"(b.y));
}
__device__ __forceinline__ uint32_t smem_u32(const void* p) {
  uint32_t a;
  asm("{ .reg .u64 t; cvta.to.shared.u64 t, %1; cvt.u32.u64 %0, t; }" : "=r"(a) : "l"(p));
  return a;
}
__device__ __forceinline__ void cpa16(uint32_t dst, const void* src) {
  asm volatile("cp.async.cg.shared.global [%0], [%1], 16;" :: "r"(dst), "l"(src));
}
#define CPA_COMMIT() asm volatile("cp.async.commit_group;" ::: "memory")
#define CPA_WAIT0()  asm volatile("cp.async.wait_group 0;" ::: "memory")

// ---------------- compaction of active (unmasked) E-rows ----------------
__global__ void k_reset() { if (threadIdx.x == 0) g_cnt = 0; }

__global__ void k_compact(const int* __restrict__ adj) {
  int i = blockIdx.x*256 + threadIdx.x;
  int lane = threadIdx.x & 31;
  int active = (adj[i] != 0);
  unsigned mask = __ballot_sync(0xffffffffu, active);
  int base = 0;
  if (lane == 0 && mask) base = atomicAdd(&g_cnt, __popc(mask));
  base = __shfl_sync(0xffffffffu, base, 0);
  if (active) g_rowidx[base + __popc(mask & ((1u << lane) - 1u))] = i;
}

__global__ void k_pad() {
  int c = g_cnt;
  int nt = (c + 127) >> 7;
  if (threadIdx.x == 0) g_ntiles = nt;
  int pad = nt*128 - c;
  if (threadIdx.x < pad) g_rowidx[c + threadIdx.x] = 0;
}

// ---------------- kernel 1: h0 = node @ W_node + b_node ----------------
__global__ void k_lin_h0(const float* __restrict__ X, const float* __restrict__ W,
                         const float* __restrict__ bias) {
  int d = threadIdx.x;
  int r0 = blockIdx.x * 8;
  __shared__ float sX[8*128];
  for (int idx = d; idx < 8*128; idx += 128) sX[idx] = X[r0*128 + idx];
  __syncthreads();
  float acc[8];
  float bv = bias[d];
#pragma unroll
  for (int r = 0; r < 8; r++) acc[r] = bv;
  for (int k = 0; k < 128; k++) {
    float w = W[k*128 + d];
#pragma unroll
    for (int r = 0; r < 8; r++) acc[r] += sX[r*128 + k] * w;
  }
#pragma unroll
  for (int r = 0; r < 8; r++) g_h0[(r0 + r)*128 + d] = acc[r];
}

// ---------------- kernel 2: Q,K,V ----------------
__global__ void k_qkv(const float* __restrict__ Wq, const float* __restrict__ bq,
                      const float* __restrict__ Wk, const float* __restrict__ bk,
                      const float* __restrict__ Wv, const float* __restrict__ bv) {
  int d = threadIdx.x;
  int r0 = blockIdx.x * 8;
  __shared__ float sX[8*128];
  for (int idx = d; idx < 8*128; idx += 128) sX[idx] = g_h0[r0*128 + idx];
  __syncthreads();
  float aq[8], ak[8], av[8];
  float bqv = bq[d], bkv = bk[d], bvv = bv[d];
#pragma unroll
  for (int r = 0; r < 8; r++) { aq[r] = bqv; ak[r] = bkv; av[r] = bvv; }
  for (int k = 0; k < 128; k++) {
    float wq = Wq[k*128 + d], wk = Wk[k*128 + d], wv = Wv[k*128 + d];
#pragma unroll
    for (int r = 0; r < 8; r++) {
      float x = sX[r*128 + k];
      aq[r] += x*wq; ak[r] += x*wk; av[r] += x*wv;
    }
  }
#pragma unroll
  for (int r = 0; r < 8; r++) {
    g_Q[(r0 + r)*128 + d] = aq[r];
    g_K[(r0 + r)*128 + d] = ak[r];
    g_V[(r0 + r)*128 + d] = av[r];
  }
}

// ---------------- kernel 3: edge_attn via fp16 m16n8k16 mma.sync ----------------
// 256 threads, warp = head, register-resident B (round-6 structure), but
// persistent over COMPACTED tiles (only unmasked rows; ~half the work).
#define EA_GRID 144
#define RAW_STRIDE  132
// smem: sA 32KB | raw 67584B | bias 1KB
#define EA_OFF_RAW  32768
#define EA_OFF_BIAS (32768 + 67584)
#define EA_SMEM     (EA_OFF_BIAS + 1024)

__global__ void __launch_bounds__(256) k_edge_attn_mma(
    const float* __restrict__ E,
    const float* __restrict__ We, const float* __restrict__ Wg,
    const float* __restrict__ be, const float* __restrict__ bg) {
  extern __shared__ char smem[];
  uint4* sA4   = (uint4*)smem;                    // [(ks*8+mt)*32+lane]
  float* raw   = (float*)(smem + EA_OFF_RAW);     // [128][RAW_STRIDE]
  float* sBias = (float*)(smem + EA_OFF_BIAS);    // be | bg
  uint32_t rawu = smem_u32(raw);

  int tid = threadIdx.x;
  int h = tid >> 5, lane = tid & 31;              // warp == head
  int g = lane >> 2, t4 = lane & 3;
  int ntiles = g_ntiles;

  if (tid < 128) { sBias[tid] = be[tid]; sBias[128 + tid] = bg[tid]; }

  // ---- load B fragments into registers (staged via raw for coalescing) ----
  uint2 Bf[2][2][8];     // [EG][nti][ks]
#pragma unroll
  for (int half = 0; half < 2; half++) {
    const float* W = half ? Wg : We;
    __syncthreads();
    for (int idx = tid; idx < 128*32; idx += 256) {
      int k = idx >> 5, c4 = idx & 31;
      float4 v = ((const float4*)W)[idx];
      *(float4*)(raw + k*RAW_STRIDE + c4*4) = v;
    }
    __syncthreads();
#pragma unroll
    for (int nti = 0; nti < 2; nti++) {
      int n = (2*h + nti)*8 + g;
#pragma unroll
      for (int ks = 0; ks < 8; ks++) {
        int k0 = ks*16 + 2*t4;
        uint32_t b0 = pack_half2(raw[k0*RAW_STRIDE + n],     raw[(k0+1)*RAW_STRIDE + n]);
        uint32_t b1 = pack_half2(raw[(k0+8)*RAW_STRIDE + n], raw[(k0+9)*RAW_STRIDE + n]);
        Bf[half][nti][ks] = make_uint2(b0, b1);
      }
    }
  }
  __syncthreads();   // raw free for E tiles

  // ---- persistent tile loop over compacted rows, double-step cp.async pipeline ----
  int t = blockIdx.x;
  if (t < ntiles) {
    for (int idx = tid; idx < 4096; idx += 256) {
      int m = idx >> 5, c4 = idx & 31;
      int row = g_rowidx[t*128 + m];        // warp-uniform
      cpa16(rawu + (uint32_t)(m*RAW_STRIDE + c4*4)*4u, E + (size_t)row*128 + c4*4);
    }
    CPA_COMMIT();
  }

  for (; t < ntiles; t += EA_GRID) {
    CPA_WAIT0();
    __syncthreads();   // raw ready; previous compute done with sA

    // convert raw fp32 -> fragment-order fp16 sA
#pragma unroll
    for (int it = 0; it < 8; it++) {
      int idx = tid + it*256;                 // 0..2047
      int lf = idx & 31, mt = (idx >> 5) & 7, ks = idx >> 8;
      int gg = lf >> 2, tt = lf & 3;
      int m0 = mt*16 + gg;
      int k0 = ks*16 + 2*tt;
      float2 x0 = *(float2*)(raw + m0*RAW_STRIDE + k0);
      float2 x1 = *(float2*)(raw + (m0+8)*RAW_STRIDE + k0);
      float2 x2 = *(float2*)(raw + m0*RAW_STRIDE + k0 + 8);
      float2 x3 = *(float2*)(raw + (m0+8)*RAW_STRIDE + k0 + 8);
      uint4 v;
      v.x = pack_half2(x0.x, x0.y);
      v.y = pack_half2(x1.x, x1.y);
      v.z = pack_half2(x2.x, x2.y);
      v.w = pack_half2(x3.x, x3.y);
      sA4[idx] = v;
    }
    __syncthreads();   // sA ready; raw free

    int tn = t + EA_GRID;
    if (tn < ntiles) {
      for (int idx = tid; idx < 4096; idx += 256) {
        int m = idx >> 5, c4 = idx & 31;
        int row = g_rowidx[tn*128 + m];
        cpa16(rawu + (uint32_t)(m*RAW_STRIDE + c4*4)*4u, E + (size_t)row*128 + c4*4);
      }
      CPA_COMMIT();
    }

    // ---- compute: two groups of 4 m-tiles; all-register B ----
#pragma unroll
    for (int grp = 0; grp < 2; grp++) {
      float aE[4][2][4], aG[4][2][4];
#pragma unroll
      for (int m4 = 0; m4 < 4; m4++)
#pragma unroll
        for (int nti = 0; nti < 2; nti++)
#pragma unroll
          for (int r = 0; r < 4; r++) { aE[m4][nti][r] = 0.f; aG[m4][nti][r] = 0.f; }

#pragma unroll
      for (int ks = 0; ks < 8; ks++) {
        uint4 a[4];
#pragma unroll
        for (int m4 = 0; m4 < 4; m4++)
          a[m4] = sA4[(ks*8 + grp*4 + m4)*32 + lane];
#pragma unroll
        for (int m4 = 0; m4 < 4; m4++) {
#pragma unroll
          for (int nti = 0; nti < 2; nti++) {
            mma16(aE[m4][nti], a[m4], Bf[0][nti][ks]);
            mma16(aG[m4][nti], a[m4], Bf[1][nti][ks]);
          }
        }
      }

      // epilogue: bias + sigmoid gate + per-head reduce over 16 dims
#pragma unroll
      for (int m4 = 0; m4 < 4; m4++) {
        int mt = grp*4 + m4;
        float s0 = 0.f, s1 = 0.f;
#pragma unroll
        for (int nti = 0; nti < 2; nti++) {
          int nb = (2*h + nti)*8 + 2*t4;
          float be0 = sBias[nb], be1 = sBias[nb+1];
          float bg0 = sBias[128+nb], bg1 = sBias[128+nb+1];
          s0 += (aE[m4][nti][0] + be0) * sigm(aG[m4][nti][0] + bg0)
              + (aE[m4][nti][1] + be1) * sigm(aG[m4][nti][1] + bg1);
          s1 += (aE[m4][nti][2] + be0) * sigm(aG[m4][nti][2] + bg0)
              + (aE[m4][nti][3] + be1) * sigm(aG[m4][nti][3] + bg1);
        }
        s0 += __shfl_xor_sync(0xffffffffu, s0, 1);
        s0 += __shfl_xor_sync(0xffffffffu, s0, 2);
        s1 += __shfl_xor_sync(0xffffffffu, s1, 1);
        s1 += __shfl_xor_sync(0xffffffffu, s1, 2);
        if (t4 == 0) {
          int slot = t*128 + mt*16 + g;
          int row0 = g_rowidx[slot];
          int row1 = g_rowidx[slot + 8];
          g_eatt[(size_t)row0*8 + h] = s0;
          g_eatt[(size_t)row1*8 + h] = s1;
        }
      }
    }
  }
}

// ---------------- kernel 4: scores + softmax + attn_mean + attn_out (tiled) ----------------
#define IPB 2
#define KPAD 132
__global__ void __launch_bounds__(256) k_attn2(const int* __restrict__ adj) {
  extern __shared__ float sm2[];
  float* sQ    = sm2;                   // IPB*128
  float* sPart = sQ + IPB*128;          // IPB*128
  float* sKV   = sPart + IPB*128;       // 64*KPAD
  float* sAtt  = sKV + 64*KPAD;         // IPB*8*Nn
  int tid = threadIdx.x;
  int bi0 = blockIdx.x * IPB;
  int b = bi0 / Nn;

  for (int idx = tid; idx < IPB*128; idx += 256) sQ[idx] = g_Q[bi0*128 + idx];
  __syncthreads();

  int jl = tid & 63, hp = tid >> 6;
  int h0 = hp*2;
  for (int jt = 0; jt < Nn/64; jt++) {
    for (int idx = tid; idx < 64*32; idx += 256) {
      int r = idx >> 5, c4 = idx & 31;
      float4 v = ((const float4*)(g_K + (size_t)(b*Nn + jt*64)*128))[idx];
      *(float4*)(sKV + r*KPAD + c4*4) = v;
    }
    __syncthreads();
    int j = jt*64 + jl;
    const float* kr = sKV + jl*KPAD;
    float a0[IPB], a1[IPB];
#pragma unroll
    for (int q = 0; q < IPB; q++) { a0[q] = 0.f; a1[q] = 0.f; }
#pragma unroll
    for (int d = 0; d < 16; d++) {
      float k0 = kr[h0*16 + d], k1 = kr[h0*16 + 16 + d];
#pragma unroll
      for (int q = 0; q < IPB; q++) {
        a0[q] += sQ[q*128 + h0*16 + d]      * k0;
        a1[q] += sQ[q*128 + h0*16 + 16 + d] * k1;
      }
    }
#pragma unroll
    for (int q = 0; q < IPB; q++) {
      int bi = bi0 + q;
      const float* er = g_eatt + ((size_t)bi*Nn + j)*8 + h0;
      float sc0 = a0[q]*0.25f + er[0];
      float sc1 = a1[q]*0.25f + er[1];
      if (adj[(size_t)bi*Nn + j] == 0) { sc0 = -1e9f; sc1 = -1e9f; }
      sAtt[(q*8 + h0)*Nn + j]     = sc0;
      sAtt[(q*8 + h0 + 1)*Nn + j] = sc1;
    }
    __syncthreads();
  }

  {
    int w = tid >> 5, lane = tid & 31;
    if (w < NHn) {
      for (int q = 0; q < IPB; q++) {
        float* rowp = sAtt + (q*8 + w)*Nn;
        float vals[12];
        float m = -1e30f;
#pragma unroll
        for (int c = 0; c < 12; c++) { vals[c] = rowp[lane + c*32]; m = fmaxf(m, vals[c]); }
#pragma unroll
        for (int off = 16; off > 0; off >>= 1) m = fmaxf(m, __shfl_xor_sync(0xffffffffu, m, off));
        float s = 0.f;
#pragma unroll
        for (int c = 0; c < 12; c++) { vals[c] = __expf(vals[c] - m); s += vals[c]; }
#pragma unroll
        for (int off = 16; off > 0; off >>= 1) s += __shfl_xor_sync(0xffffffffu, s, off);
        float inv = 1.f / s;
#pragma unroll
        for (int c = 0; c < 12; c++) rowp[lane + c*32] = vals[c] * inv;
      }
    }
  }
  __syncthreads();

  for (int idx = tid; idx < IPB*Nn; idx += 256) {
    int q = idx / Nn, j = idx % Nn;
    float s = 0.f;
#pragma unroll
    for (int h = 0; h < 8; h++) s += sAtt[(q*8 + h)*Nn + j];
    g_amean[(size_t)(bi0 + q)*Nn + j] = s * (1.f/NHn);
  }

  int d = tid & 127, half = tid >> 7;
  int hc = d >> 4;
  float acc[IPB];
#pragma unroll
  for (int q = 0; q < IPB; q++) acc[q] = 0.f;
  for (int jt = 0; jt < Nn/64; jt++) {
    __syncthreads();
    for (int idx = tid; idx < 64*32; idx += 256) {
      int r = idx >> 5, c4 = idx & 31;
      float4 v = ((const float4*)(g_V + (size_t)(b*Nn + jt*64)*128))[idx];
      *(float4*)(sKV + r*KPAD + c4*4) = v;
    }
    __syncthreads();
#pragma unroll 8
    for (int jj = half*32; jj < half*32 + 32; jj++) {
      float v = sKV[jj*KPAD + d];
      int j = jt*64 + jj;
#pragma unroll
      for (int q = 0; q < IPB; q++) acc[q] += sAtt[(q*8 + hc)*Nn + j] * v;
    }
  }
  __syncthreads();
  if (half == 1) {
#pragma unroll
    for (int q = 0; q < IPB; q++) sPart[q*128 + d] = acc[q];
  }
  __syncthreads();
  if (half == 0) {
#pragma unroll
    for (int q = 0; q < IPB; q++)
      g_attO[(size_t)(bi0 + q)*128 + d] = acc[q] + sPart[q*128 + d];
  }
}

// ---------------- kernel 5: h = LN(h0 + attO@W_out + b_out); hW = h @ W_eout ----------------
__global__ void k_hout(const float* __restrict__ Wout, const float* __restrict__ bout,
                       const float* __restrict__ g1, const float* __restrict__ be1,
                       const float* __restrict__ Weout, float* __restrict__ outH) {
  int row = blockIdx.x;
  int d = threadIdx.x;
  int lane = d & 31, w = d >> 5;
  __shared__ float sIn[128];
  __shared__ float sRow[128];
  __shared__ float sS[4], sQ2[4];
  sIn[d] = g_attO[row*128 + d];
  __syncthreads();
  float acc = bout[d];
#pragma unroll 4
  for (int k = 0; k < 128; k++) acc += sIn[k] * Wout[k*128 + d];
  float r = acc + g_h0[row*128 + d];
  float v = r, q = r*r;
#pragma unroll
  for (int off = 16; off > 0; off >>= 1) {
    v += __shfl_xor_sync(0xffffffffu, v, off);
    q += __shfl_xor_sync(0xffffffffu, q, off);
  }
  if (lane == 0) { sS[w] = v; sQ2[w] = q; }
  __syncthreads();
  float tot  = sS[0] + sS[1] + sS[2] + sS[3];
  float totq = sQ2[0] + sQ2[1] + sQ2[2] + sQ2[3];
  float mean = tot * (1.f/128.f);
  float var  = totq * (1.f/128.f) - mean*mean;
  float y = (r - mean) * rsqrtf(var + 1e-5f) * g1[d] + be1[d];
  outH[row*128 + d] = y;
  sRow[d] = y;
  __syncthreads();
  float acc2 = 0.f;
#pragma unroll 4
  for (int k = 0; k < 128; k++) acc2 += sRow[k] * Weout[k*128 + d];
  g_hW[row*128 + d] = acc2;
}

// ---------------- kernel 6: edge_out = LN(E + amean*0.5*(hW_i+hW_j) + b_eout) ----------------
__global__ void k_edge_out(const float* __restrict__ Ef, const float* __restrict__ beout,
                           const float* __restrict__ g2, const float* __restrict__ be2,
                           float* __restrict__ outE) {
  int warp = threadIdx.x >> 5, lane = threadIdx.x & 31;
  size_t row = (size_t)blockIdx.x * 8 + warp;
  int b  = (int)(row / (Nn*Nn));
  int ij = (int)(row % (Nn*Nn));
  int i = ij / Nn, j = ij % Nn;
  float am = g_amean[row] * 0.5f;
  float4 e  = ((const float4*)(Ef + row*128))[lane];
  float4 ui = ((const float4*)(g_hW + (size_t)(b*Nn + i)*128))[lane];
  float4 uj = ((const float4*)(g_hW + (size_t)(b*Nn + j)*128))[lane];
  float4 bo = ((const float4*)beout)[lane];
  float v0 = e.x + am*(ui.x + uj.x) + bo.x;
  float v1 = e.y + am*(ui.y + uj.y) + bo.y;
  float v2 = e.z + am*(ui.z + uj.z) + bo.z;
  float v3 = e.w + am*(ui.w + uj.w) + bo.w;
  float s = v0 + v1 + v2 + v3;
  float q = v0*v0 + v1*v1 + v2*v2 + v3*v3;
#pragma unroll
  for (int off = 16; off > 0; off >>= 1) {
    s += __shfl_xor_sync(0xffffffffu, s, off);
    q += __shfl_xor_sync(0xffffffffu, q, off);
  }
  float mean = s * (1.f/128.f);
  float var  = q * (1.f/128.f) - mean*mean;
  float inv  = rsqrtf(var + 1e-5f);
  float4 gg = ((const float4*)g2)[lane];
  float4 bb = ((const float4*)be2)[lane];
  float4 o;
  o.x = (v0 - mean)*inv*gg.x + bb.x;
  o.y = (v1 - mean)*inv*gg.y + bb.y;
  o.z = (v2 - mean)*inv*gg.z + bb.z;
  o.w = (v3 - mean)*inv*gg.w + bb.w;
  ((float4*)outE)[row*32 + lane] = o;
}

// ---------------- launcher ----------------
extern "C" void kernel_launch(void* const* d_in, const int* in_sizes, int n_in,
                              void* d_out, int out_size) {
  const float* node   = (const float*)d_in[0];
  const float* edge   = (const float*)d_in[1];
  const int*   adj    = (const int*)  d_in[2];
  const float* W_node = (const float*)d_in[3];  const float* b_node = (const float*)d_in[4];
  const float* W_q    = (const float*)d_in[5];  const float* b_q    = (const float*)d_in[6];
  const float* W_k    = (const float*)d_in[7];  const float* b_k    = (const float*)d_in[8];
  const float* W_v    = (const float*)d_in[9];  const float* b_v    = (const float*)d_in[10];
  const float* W_edge = (const float*)d_in[11]; const float* b_edge = (const float*)d_in[12];
  const float* W_gate = (const float*)d_in[13]; const float* b_gate = (const float*)d_in[14];
  const float* W_out  = (const float*)d_in[15]; const float* b_out  = (const float*)d_in[16];
  const float* W_eout = (const float*)d_in[17]; const float* b_eout = (const float*)d_in[18];
  const float* g1     = (const float*)d_in[19]; const float* be1    = (const float*)d_in[20];
  const float* g2     = (const float*)d_in[21]; const float* be2    = (const float*)d_in[22];

  float* outH = (float*)d_out;
  float* outE = outH + HROWS*HIDn;

  cudaFuncSetAttribute(k_edge_attn_mma, cudaFuncAttributeMaxDynamicSharedMemorySize, EA_SMEM);
  cudaFuncSetAttribute(k_attn2, cudaFuncAttributeMaxDynamicSharedMemorySize, 128*1024);

  int attn_smem = (IPB*128 + IPB*128 + 64*KPAD + IPB*8*Nn) * 4;

  k_reset<<<1, 32>>>();
  k_compact<<<EROWS/256, 256>>>(adj);
  k_pad<<<1, 128>>>();
  k_lin_h0<<<HROWS/8, 128>>>(node, W_node, b_node);
  k_qkv<<<HROWS/8, 128>>>(W_q, b_q, W_k, b_k, W_v, b_v);
  k_edge_attn_mma<<<EA_GRID, 256, EA_SMEM>>>(edge, W_edge, W_gate, b_edge, b_gate);
  k_attn2<<<HROWS/IPB, 256, attn_smem>>>(adj);
  k_hout<<<HROWS, 128>>>(W_out, b_out, g1, be1, W_eout, outH);
  k_edge_out<<<EROWS/8, 256>>>(edge, b_eout, g2, be2, outE);
}

// round 10
// speedup vs baseline: 1.7128x; 1.0433x over previous
#include <cuda_runtime.h>
#include <cstdint>
#include <math.h>

#define Bn    2
#define Nn    384
#define HIDn  128
#define NHn   8
#define HDn   16
#define HROWS (Bn*Nn)          // 768
#define EROWS (Bn*Nn*Nn)       // 294912

// ---------------- scratch (static device globals; no allocations) ----------------
__device__ float g_h0[HROWS*HIDn];
__device__ float g_Q[HROWS*HIDn];
__device__ float g_K[HROWS*HIDn];
__device__ float g_V[HROWS*HIDn];
__device__ float g_eatt[(size_t)EROWS*NHn];   // (b,i,j,h) contiguous h
__device__ float g_amean[EROWS];
__device__ float g_attO[HROWS*HIDn];
__device__ float g_hW[HROWS*HIDn];
__device__ int   g_cnt;
__device__ int   g_ntiles;
__device__ int   g_rowidx[EROWS + 128];

// ================= helpers =================
__device__ __forceinline__ float sigm(float x) { return 1.f / (1.f + __expf(-x)); }
__device__ __forceinline__ uint32_t pack_half2(float lo, float hi) {
  uint32_t r;
  asm("cvt.rn.f16x2.f32 %0, %1, %2;" : "=r"(r) : "f"(hi), "f"(lo));
  return r;
}
__device__ __forceinline__ void mma16(float* d, const uint4 a, const uint2 b) {
  asm volatile("mma.sync.aligned.m16n8k16.row.col.f32.f16.f16.f32 "
    "{%0,%1,%2,%3},{%4,%5,%6,%7},{%8,%9},{%0,%1,%2,%3};"
    : "+f"(d[0]), "+f"(d[1]), "+f"(d[2]), "+f"(d[3])
    : "r"(a.x), "r"(a.y), "r"(a.z), "r"(a.w), "r"(b.x), "r"(b.y));
}
__device__ __forceinline__ uint32_t smem_u32(const void* p) {
  uint32_t a;
  asm("{ .reg .u64 t; cvta.to.shared.u64 t, %1; cvt.u32.u64 %0, t; }" : "=r"(a) : "l"(p));
  return a;
}
__device__ __forceinline__ void cpa16(uint32_t dst, const void* src) {
  asm volatile("cp.async.cg.shared.global [%0], [%1], 16;" :: "r"(dst), "l"(src));
}
#define CPA_COMMIT() asm volatile("cp.async.commit_group;" ::: "memory")
#define CPA_WAIT0()  asm volatile("cp.async.wait_group 0;" ::: "memory")

// ---------------- compaction of active (unmasked) E-rows ----------------
__global__ void k_compact(const int* __restrict__ adj) {
  int i = blockIdx.x*256 + threadIdx.x;
  int lane = threadIdx.x & 31;
  int active = (adj[i] != 0);
  unsigned mask = __ballot_sync(0xffffffffu, active);
  int base = 0;
  if (lane == 0 && mask) base = atomicAdd(&g_cnt, __popc(mask));
  base = __shfl_sync(0xffffffffu, base, 0);
  if (active) g_rowidx[base + __popc(mask & ((1u << lane) - 1u))] = i;
}

__global__ void k_pad() {
  int c = g_cnt;
  int nt = (c + 127) >> 7;
  if (threadIdx.x == 0) g_ntiles = nt;
  int pad = nt*128 - c;
  if (threadIdx.x < pad) g_rowidx[c + threadIdx.x] = 0;
}

// ---------------- kernel 1: fused h0 = X@Wn+bn ; Q,K,V = h0@{Wq,Wk,Wv}+b ----------------
// 96 blocks x 256 threads; 8 rows per block; half-warpsets split rows 0-3 / 4-7
// sharing the same W column loads (L1 broadcast). Also resets g_cnt (block 0).
__global__ void __launch_bounds__(256) k_node_qkv(
    const float* __restrict__ X,
    const float* __restrict__ Wn, const float* __restrict__ bn,
    const float* __restrict__ Wq, const float* __restrict__ bq,
    const float* __restrict__ Wk, const float* __restrict__ bk,
    const float* __restrict__ Wv, const float* __restrict__ bv) {
  __shared__ float sX[8*128];
  __shared__ float sH[8*128];
  int tid = threadIdx.x;
  int r0 = blockIdx.x * 8;
  if (blockIdx.x == 0 && tid == 0) g_cnt = 0;   // reset for k_compact (stream-ordered)
  for (int idx = tid; idx < 8*128; idx += 256) sX[idx] = X[r0*128 + idx];
  __syncthreads();

  int d = tid & 127, half = tid >> 7;           // half: rows 4*half .. 4*half+3
  const float* xr = sX + half*4*128;

  // step 1: h0 rows
  float acc[4];
  {
    float bv0 = bn[d];
#pragma unroll
    for (int r = 0; r < 4; r++) acc[r] = bv0;
#pragma unroll 4
    for (int k = 0; k < 128; k++) {
      float w = Wn[k*128 + d];
#pragma unroll
      for (int r = 0; r < 4; r++) acc[r] += xr[r*128 + k] * w;
    }
#pragma unroll
    for (int r = 0; r < 4; r++) {
      sH[(half*4 + r)*128 + d] = acc[r];
      g_h0[(r0 + half*4 + r)*128 + d] = acc[r];
    }
  }
  __syncthreads();

  // step 2: Q,K,V rows
  const float* hr = sH + half*4*128;
  float aq[4], ak[4], av[4];
  float bqv = bq[d], bkv = bk[d], bvv = bv[d];
#pragma unroll
  for (int r = 0; r < 4; r++) { aq[r] = bqv; ak[r] = bkv; av[r] = bvv; }
#pragma unroll 4
  for (int k = 0; k < 128; k++) {
    float wq = Wq[k*128 + d], wk = Wk[k*128 + d], wv = Wv[k*128 + d];
#pragma unroll
    for (int r = 0; r < 4; r++) {
      float x = hr[r*128 + k];
      aq[r] += x*wq; ak[r] += x*wk; av[r] += x*wv;
    }
  }
#pragma unroll
  for (int r = 0; r < 4; r++) {
    int row = r0 + half*4 + r;
    g_Q[row*128 + d] = aq[r];
    g_K[row*128 + d] = ak[r];
    g_V[row*128 + d] = av[r];
  }
}

// ---------------- kernel 3: edge_attn via fp16 m16n8k16 mma.sync ----------------
// 256 threads, warp = head, register-resident B; persistent over COMPACTED tiles.
#define EA_GRID 148
#define RAW_STRIDE  132
// smem: sA 32KB | raw 67584B | bias 1KB
#define EA_OFF_RAW  32768
#define EA_OFF_BIAS (32768 + 67584)
#define EA_SMEM     (EA_OFF_BIAS + 1024)

__global__ void __launch_bounds__(256) k_edge_attn_mma(
    const float* __restrict__ E,
    const float* __restrict__ We, const float* __restrict__ Wg,
    const float* __restrict__ be, const float* __restrict__ bg) {
  extern __shared__ char smem[];
  uint4* sA4   = (uint4*)smem;                    // [(ks*8+mt)*32+lane]
  float* raw   = (float*)(smem + EA_OFF_RAW);     // [128][RAW_STRIDE]
  float* sBias = (float*)(smem + EA_OFF_BIAS);    // be | bg
  uint32_t rawu = smem_u32(raw);

  int tid = threadIdx.x;
  int h = tid >> 5, lane = tid & 31;              // warp == head
  int g = lane >> 2, t4 = lane & 3;
  int ntiles = g_ntiles;

  if (tid < 128) { sBias[tid] = be[tid]; sBias[128 + tid] = bg[tid]; }

  // ---- load B fragments into registers (staged via raw for coalescing) ----
  uint2 Bf[2][2][8];     // [EG][nti][ks]
#pragma unroll
  for (int half = 0; half < 2; half++) {
    const float* W = half ? Wg : We;
    __syncthreads();
    for (int idx = tid; idx < 128*32; idx += 256) {
      int k = idx >> 5, c4 = idx & 31;
      float4 v = ((const float4*)W)[idx];
      *(float4*)(raw + k*RAW_STRIDE + c4*4) = v;
    }
    __syncthreads();
#pragma unroll
    for (int nti = 0; nti < 2; nti++) {
      int n = (2*h + nti)*8 + g;
#pragma unroll
      for (int ks = 0; ks < 8; ks++) {
        int k0 = ks*16 + 2*t4;
        uint32_t b0 = pack_half2(raw[k0*RAW_STRIDE + n],     raw[(k0+1)*RAW_STRIDE + n]);
        uint32_t b1 = pack_half2(raw[(k0+8)*RAW_STRIDE + n], raw[(k0+9)*RAW_STRIDE + n]);
        Bf[half][nti][ks] = make_uint2(b0, b1);
      }
    }
  }
  __syncthreads();   // raw free for E tiles

  // ---- persistent tile loop over compacted rows, double-step cp.async pipeline ----
  int t = blockIdx.x;
  if (t < ntiles) {
    for (int idx = tid; idx < 4096; idx += 256) {
      int m = idx >> 5, c4 = idx & 31;
      int row = g_rowidx[t*128 + m];        // warp-uniform
      cpa16(rawu + (uint32_t)(m*RAW_STRIDE + c4*4)*4u, E + (size_t)row*128 + c4*4);
    }
    CPA_COMMIT();
  }

  for (; t < ntiles; t += EA_GRID) {
    CPA_WAIT0();
    __syncthreads();   // raw ready; previous compute done with sA

    // convert raw fp32 -> fragment-order fp16 sA
#pragma unroll
    for (int it = 0; it < 8; it++) {
      int idx = tid + it*256;                 // 0..2047
      int lf = idx & 31, mt = (idx >> 5) & 7, ks = idx >> 8;
      int gg = lf >> 2, tt = lf & 3;
      int m0 = mt*16 + gg;
      int k0 = ks*16 + 2*tt;
      float2 x0 = *(float2*)(raw + m0*RAW_STRIDE + k0);
      float2 x1 = *(float2*)(raw + (m0+8)*RAW_STRIDE + k0);
      float2 x2 = *(float2*)(raw + m0*RAW_STRIDE + k0 + 8);
      float2 x3 = *(float2*)(raw + (m0+8)*RAW_STRIDE + k0 + 8);
      uint4 v;
      v.x = pack_half2(x0.x, x0.y);
      v.y = pack_half2(x1.x, x1.y);
      v.z = pack_half2(x2.x, x2.y);
      v.w = pack_half2(x3.x, x3.y);
      sA4[idx] = v;
    }
    __syncthreads();   // sA ready; raw free

    int tn = t + EA_GRID;
    if (tn < ntiles) {
      for (int idx = tid; idx < 4096; idx += 256) {
        int m = idx >> 5, c4 = idx & 31;
        int row = g_rowidx[tn*128 + m];
        cpa16(rawu + (uint32_t)(m*RAW_STRIDE + c4*4)*4u, E + (size_t)row*128 + c4*4);
      }
      CPA_COMMIT();
    }

    // ---- compute: two groups of 4 m-tiles; all-register B ----
#pragma unroll
    for (int grp = 0; grp < 2; grp++) {
      float aE[4][2][4], aG[4][2][4];
#pragma unroll
      for (int m4 = 0; m4 < 4; m4++)
#pragma unroll
        for (int nti = 0; nti < 2; nti++)
#pragma unroll
          for (int r = 0; r < 4; r++) { aE[m4][nti][r] = 0.f; aG[m4][nti][r] = 0.f; }

#pragma unroll
      for (int ks = 0; ks < 8; ks++) {
        uint4 a[4];
#pragma unroll
        for (int m4 = 0; m4 < 4; m4++)
          a[m4] = sA4[(ks*8 + grp*4 + m4)*32 + lane];
#pragma unroll
        for (int m4 = 0; m4 < 4; m4++) {
#pragma unroll
          for (int nti = 0; nti < 2; nti++) {
            mma16(aE[m4][nti], a[m4], Bf[0][nti][ks]);
            mma16(aG[m4][nti], a[m4], Bf[1][nti][ks]);
          }
        }
      }

      // epilogue: bias + sigmoid gate + per-head reduce over 16 dims
#pragma unroll
      for (int m4 = 0; m4 < 4; m4++) {
        int mt = grp*4 + m4;
        float s0 = 0.f, s1 = 0.f;
#pragma unroll
        for (int nti = 0; nti < 2; nti++) {
          int nb = (2*h + nti)*8 + 2*t4;
          float be0 = sBias[nb], be1 = sBias[nb+1];
          float bg0 = sBias[128+nb], bg1 = sBias[128+nb+1];
          s0 += (aE[m4][nti][0] + be0) * sigm(aG[m4][nti][0] + bg0)
              + (aE[m4][nti][1] + be1) * sigm(aG[m4][nti][1] + bg1);
          s1 += (aE[m4][nti][2] + be0) * sigm(aG[m4][nti][2] + bg0)
              + (aE[m4][nti][3] + be1) * sigm(aG[m4][nti][3] + bg1);
        }
        s0 += __shfl_xor_sync(0xffffffffu, s0, 1);
        s0 += __shfl_xor_sync(0xffffffffu, s0, 2);
        s1 += __shfl_xor_sync(0xffffffffu, s1, 1);
        s1 += __shfl_xor_sync(0xffffffffu, s1, 2);
        if (t4 == 0) {
          int slot = t*128 + mt*16 + g;
          int row0 = g_rowidx[slot];
          int row1 = g_rowidx[slot + 8];
          g_eatt[(size_t)row0*8 + h] = s0;
          g_eatt[(size_t)row1*8 + h] = s1;
        }
      }
    }
  }
}

// ---------------- kernel 4: scores + softmax + attn_mean + attn_out (tiled) ----------------
#define IPB 2
#define KPAD 132
__global__ void __launch_bounds__(256) k_attn2(const int* __restrict__ adj) {
  extern __shared__ float sm2[];
  float* sQ    = sm2;                   // IPB*128
  float* sPart = sQ + IPB*128;          // IPB*128
  float* sKV   = sPart + IPB*128;       // 64*KPAD
  float* sAtt  = sKV + 64*KPAD;         // IPB*8*Nn
  int tid = threadIdx.x;
  int bi0 = blockIdx.x * IPB;
  int b = bi0 / Nn;

  for (int idx = tid; idx < IPB*128; idx += 256) sQ[idx] = g_Q[bi0*128 + idx];
  __syncthreads();

  int jl = tid & 63, hp = tid >> 6;
  int h0 = hp*2;
  for (int jt = 0; jt < Nn/64; jt++) {
    for (int idx = tid; idx < 64*32; idx += 256) {
      int r = idx >> 5, c4 = idx & 31;
      float4 v = ((const float4*)(g_K + (size_t)(b*Nn + jt*64)*128))[idx];
      *(float4*)(sKV + r*KPAD + c4*4) = v;
    }
    __syncthreads();
    int j = jt*64 + jl;
    const float* kr = sKV + jl*KPAD;
    float a0[IPB], a1[IPB];
#pragma unroll
    for (int q = 0; q < IPB; q++) { a0[q] = 0.f; a1[q] = 0.f; }
#pragma unroll
    for (int d = 0; d < 16; d++) {
      float k0 = kr[h0*16 + d], k1 = kr[h0*16 + 16 + d];
#pragma unroll
      for (int q = 0; q < IPB; q++) {
        a0[q] += sQ[q*128 + h0*16 + d]      * k0;
        a1[q] += sQ[q*128 + h0*16 + 16 + d] * k1;
      }
    }
#pragma unroll
    for (int q = 0; q < IPB; q++) {
      int bi = bi0 + q;
      const float* er = g_eatt + ((size_t)bi*Nn + j)*8 + h0;
      float sc0 = a0[q]*0.25f + er[0];
      float sc1 = a1[q]*0.25f + er[1];
      if (adj[(size_t)bi*Nn + j] == 0) { sc0 = -1e9f; sc1 = -1e9f; }
      sAtt[(q*8 + h0)*Nn + j]     = sc0;
      sAtt[(q*8 + h0 + 1)*Nn + j] = sc1;
    }
    __syncthreads();
  }

  {
    int w = tid >> 5, lane = tid & 31;
    if (w < NHn) {
      for (int q = 0; q < IPB; q++) {
        float* rowp = sAtt + (q*8 + w)*Nn;
        float vals[12];
        float m = -1e30f;
#pragma unroll
        for (int c = 0; c < 12; c++) { vals[c] = rowp[lane + c*32]; m = fmaxf(m, vals[c]); }
#pragma unroll
        for (int off = 16; off > 0; off >>= 1) m = fmaxf(m, __shfl_xor_sync(0xffffffffu, m, off));
        float s = 0.f;
#pragma unroll
        for (int c = 0; c < 12; c++) { vals[c] = __expf(vals[c] - m); s += vals[c]; }
#pragma unroll
        for (int off = 16; off > 0; off >>= 1) s += __shfl_xor_sync(0xffffffffu, s, off);
        float inv = 1.f / s;
#pragma unroll
        for (int c = 0; c < 12; c++) rowp[lane + c*32] = vals[c] * inv;
      }
    }
  }
  __syncthreads();

  for (int idx = tid; idx < IPB*Nn; idx += 256) {
    int q = idx / Nn, j = idx % Nn;
    float s = 0.f;
#pragma unroll
    for (int h = 0; h < 8; h++) s += sAtt[(q*8 + h)*Nn + j];
    g_amean[(size_t)(bi0 + q)*Nn + j] = s * (1.f/NHn);
  }

  int d = tid & 127, half = tid >> 7;
  int hc = d >> 4;
  float acc[IPB];
#pragma unroll
  for (int q = 0; q < IPB; q++) acc[q] = 0.f;
  for (int jt = 0; jt < Nn/64; jt++) {
    __syncthreads();
    for (int idx = tid; idx < 64*32; idx += 256) {
      int r = idx >> 5, c4 = idx & 31;
      float4 v = ((const float4*)(g_V + (size_t)(b*Nn + jt*64)*128))[idx];
      *(float4*)(sKV + r*KPAD + c4*4) = v;
    }
    __syncthreads();
#pragma unroll 8
    for (int jj = half*32; jj < half*32 + 32; jj++) {
      float v = sKV[jj*KPAD + d];
      int j = jt*64 + jj;
#pragma unroll
      for (int q = 0; q < IPB; q++) acc[q] += sAtt[(q*8 + hc)*Nn + j] * v;
    }
  }
  __syncthreads();
  if (half == 1) {
#pragma unroll
    for (int q = 0; q < IPB; q++) sPart[q*128 + d] = acc[q];
  }
  __syncthreads();
  if (half == 0) {
#pragma unroll
    for (int q = 0; q < IPB; q++)
      g_attO[(size_t)(bi0 + q)*128 + d] = acc[q] + sPart[q*128 + d];
  }
}

// ---------------- kernel 5: h = LN(h0 + attO@W_out + b_out); hW = h @ W_eout ----------------
__global__ void k_hout(const float* __restrict__ Wout, const float* __restrict__ bout,
                       const float* __restrict__ g1, const float* __restrict__ be1,
                       const float* __restrict__ Weout, float* __restrict__ outH) {
  int row = blockIdx.x;
  int d = threadIdx.x;
  int lane = d & 31, w = d >> 5;
  __shared__ float sIn[128];
  __shared__ float sRow[128];
  __shared__ float sS[4], sQ2[4];
  sIn[d] = g_attO[row*128 + d];
  __syncthreads();
  float acc = bout[d];
#pragma unroll 4
  for (int k = 0; k < 128; k++) acc += sIn[k] * Wout[k*128 + d];
  float r = acc + g_h0[row*128 + d];
  float v = r, q = r*r;
#pragma unroll
  for (int off = 16; off > 0; off >>= 1) {
    v += __shfl_xor_sync(0xffffffffu, v, off);
    q += __shfl_xor_sync(0xffffffffu, q, off);
  }
  if (lane == 0) { sS[w] = v; sQ2[w] = q; }
  __syncthreads();
  float tot  = sS[0] + sS[1] + sS[2] + sS[3];
  float totq = sQ2[0] + sQ2[1] + sQ2[2] + sQ2[3];
  float mean = tot * (1.f/128.f);
  float var  = totq * (1.f/128.f) - mean*mean;
  float y = (r - mean) * rsqrtf(var + 1e-5f) * g1[d] + be1[d];
  outH[row*128 + d] = y;
  sRow[d] = y;
  __syncthreads();
  float acc2 = 0.f;
#pragma unroll 4
  for (int k = 0; k < 128; k++) acc2 += sRow[k] * Weout[k*128 + d];
  g_hW[row*128 + d] = acc2;
}

// ---------------- kernel 6: edge_out = LN(E + amean*0.5*(hW_i+hW_j) + b_eout) ----------------
__global__ void k_edge_out(const float* __restrict__ Ef, const float* __restrict__ beout,
                           const float* __restrict__ g2, const float* __restrict__ be2,
                           float* __restrict__ outE) {
  int warp = threadIdx.x >> 5, lane = threadIdx.x & 31;
  size_t row = (size_t)blockIdx.x * 8 + warp;
  int b  = (int)(row / (Nn*Nn));
  int ij = (int)(row % (Nn*Nn));
  int i = ij / Nn, j = ij % Nn;
  float am = g_amean[row] * 0.5f;
  float4 e  = ((const float4*)(Ef + row*128))[lane];
  float4 ui = ((const float4*)(g_hW + (size_t)(b*Nn + i)*128))[lane];
  float4 uj = ((const float4*)(g_hW + (size_t)(b*Nn + j)*128))[lane];
  float4 bo = ((const float4*)beout)[lane];
  float v0 = e.x + am*(ui.x + uj.x) + bo.x;
  float v1 = e.y + am*(ui.y + uj.y) + bo.y;
  float v2 = e.z + am*(ui.z + uj.z) + bo.z;
  float v3 = e.w + am*(ui.w + uj.w) + bo.w;
  float s = v0 + v1 + v2 + v3;
  float q = v0*v0 + v1*v1 + v2*v2 + v3*v3;
#pragma unroll
  for (int off = 16; off > 0; off >>= 1) {
    s += __shfl_xor_sync(0xffffffffu, s, off);
    q += __shfl_xor_sync(0xffffffffu, q, off);
  }
  float mean = s * (1.f/128.f);
  float var  = q * (1.f/128.f) - mean*mean;
  float inv  = rsqrtf(var + 1e-5f);
  float4 gg = ((const float4*)g2)[lane];
  float4 bb = ((const float4*)be2)[lane];
  float4 o;
  o.x = (v0 - mean)*inv*gg.x + bb.x;
  o.y = (v1 - mean)*inv*gg.y + bb.y;
  o.z = (v2 - mean)*inv*gg.z + bb.z;
  o.w = (v3 - mean)*inv*gg.w + bb.w;
  ((float4*)outE)[row*32 + lane] = o;
}

// ---------------- launcher ----------------
extern "C" void kernel_launch(void* const* d_in, const int* in_sizes, int n_in,
                              void* d_out, int out_size) {
  const float* node   = (const float*)d_in[0];
  const float* edge   = (const float*)d_in[1];
  const int*   adj    = (const int*)  d_in[2];
  const float* W_node = (const float*)d_in[3];  const float* b_node = (const float*)d_in[4];
  const float* W_q    = (const float*)d_in[5];  const float* b_q    = (const float*)d_in[6];
  const float* W_k    = (const float*)d_in[7];  const float* b_k    = (const float*)d_in[8];
  const float* W_v    = (const float*)d_in[9];  const float* b_v    = (const float*)d_in[10];
  const float* W_edge = (const float*)d_in[11]; const float* b_edge = (const float*)d_in[12];
  const float* W_gate = (const float*)d_in[13]; const float* b_gate = (const float*)d_in[14];
  const float* W_out  = (const float*)d_in[15]; const float* b_out  = (const float*)d_in[16];
  const float* W_eout = (const float*)d_in[17]; const float* b_eout = (const float*)d_in[18];
  const float* g1     = (const float*)d_in[19]; const float* be1    = (const float*)d_in[20];
  const float* g2     = (const float*)d_in[21]; const float* be2    = (const float*)d_in[22];

  float* outH = (float*)d_out;
  float* outE = outH + HROWS*HIDn;

  cudaFuncSetAttribute(k_edge_attn_mma, cudaFuncAttributeMaxDynamicSharedMemorySize, EA_SMEM);
  cudaFuncSetAttribute(k_attn2, cudaFuncAttributeMaxDynamicSharedMemorySize, 128*1024);

  int attn_smem = (IPB*128 + IPB*128 + 64*KPAD + IPB*8*Nn) * 4;

  k_node_qkv<<<HROWS/8, 256>>>(node, W_node, b_node, W_q, b_q, W_k, b_k, W_v, b_v);
  k_compact<<<EROWS/256, 256>>>(adj);
  k_pad<<<1, 128>>>();
  k_edge_attn_mma<<<EA_GRID, 256, EA_SMEM>>>(edge, W_edge, W_gate, b_edge, b_gate);
  k_attn2<<<HROWS/IPB, 256, attn_smem>>>(adj);
  k_hout<<<HROWS, 128>>>(W_out, b_out, g1, be1, W_eout, outH);
  k_edge_out<<<EROWS/8, 256>>>(edge, b_eout, g2, be2, outE);
}